// round 1
// baseline (speedup 1.0000x reference)
#include <cuda_runtime.h>
#include <cuda_bf16.h>
#include <cstdint>

typedef unsigned long long ull;

// Problem constants
#define BB 4
#define NN 256
#define EE 63
#define DD 64
#define HH 128

#define TILES_PER_B 1152        // sum over i of ceil((256-i)/32)
#define NTILES (BB * TILES_PER_B)
#define GRID1 152               // persistent CTAs (one per GB300 SM)
#define MPAD 34                 // padded M stride (bank-conflict-free b64 loads/stores)

// Scratch (no allocations allowed)
__device__ float g_x[BB * NN * DD];              // 256 KB
__device__ float g_partial[GRID1 * BB * HH];     // per-CTA partial sums

// ---------------- f32x2 helpers (sm_103a packed fp32) ----------------
__device__ __forceinline__ ull fpack(float lo, float hi) {
    ull r; asm("mov.b64 %0, {%1, %2};" : "=l"(r) : "f"(lo), "f"(hi)); return r;
}
__device__ __forceinline__ void fma2(ull& d, ull a, ull b) {
    asm("fma.rn.f32x2 %0, %1, %2, %0;" : "+l"(d) : "l"(a), "l"(b));
}
__device__ __forceinline__ float2 funpack(ull p) {
    float2 r; asm("mov.b64 {%0, %1}, %2;" : "=f"(r.x), "=f"(r.y) : "l"(p)); return r;
}

// ---------------- Kernel 0: build x = concat(emb[xcat], xfeat) ----------------
__global__ void build_x_kernel(const int* __restrict__ xcat32,
                               const float* __restrict__ xfeat,
                               const float* __restrict__ emb) {
    int row = blockIdx.x;        // 0..1023 = b*256 + n
    int d = threadIdx.x;         // 0..63
    // int64-vs-int32 detection: if source is int64 (<10000), all odd 32-bit
    // words are 0. For int32 random data the probability of this is ~1e-24.
    bool is64 = (xcat32[1] == 0) && (xcat32[3] == 0) && (xcat32[5] == 0) &&
                (xcat32[7] == 0) && (xcat32[9] == 0) && (xcat32[11] == 0);
    int idx = is64 ? xcat32[row * 2] : xcat32[row];
    float v = (d < EE) ? emb[idx * EE + d] : xfeat[row];
    g_x[row * DD + d] = v;
}

// ---------------- GEMM core: 32 pairs x 128 feats, K-major act in smem ----------------
// Thread (pg, fg): pg = tid>>6 in [0,4) owns pairs pg*8..pg*8+7,
//                  fg = tid&63 owns features fg and fg+64.
// acc[mp][fi] packs pairs (2mp, 2mp+1) for feature fi.
template <int K>
__device__ __forceinline__ void gemm_acc(const float* __restrict__ act,   // [K][MPAD] smem
                                         const float* __restrict__ Ws,    // [K][128] smem
                                         int pg, int fg,
                                         float bias0, float bias1,
                                         ull acc[4][2]) {
    ull bp0 = fpack(bias0, bias0), bp1 = fpack(bias1, bias1);
#pragma unroll
    for (int mp = 0; mp < 4; mp++) { acc[mp][0] = bp0; acc[mp][1] = bp1; }
    const float* ap = act + pg * 8;
    const float* wp = Ws + fg;
#pragma unroll 8
    for (int k = 0; k < K; k++) {
        ull a0 = *(const ull*)(ap + 0);
        ull a1 = *(const ull*)(ap + 2);
        ull a2 = *(const ull*)(ap + 4);
        ull a3 = *(const ull*)(ap + 6);
        float w0 = wp[0], w1 = wp[64];
        ull wq0 = fpack(w0, w0), wq1 = fpack(w1, w1);
        fma2(acc[0][0], a0, wq0); fma2(acc[1][0], a1, wq0);
        fma2(acc[2][0], a2, wq0); fma2(acc[3][0], a3, wq0);
        fma2(acc[0][1], a0, wq1); fma2(acc[1][1], a1, wq1);
        fma2(acc[2][1], a2, wq1); fma2(acc[3][1], a3, wq1);
        ap += MPAD; wp += HH;
    }
}

__device__ __forceinline__ void store_relu(float* __restrict__ out, int pg, int fg,
                                           ull acc[4][2]) {
    float* o0 = out + fg * MPAD + pg * 8;
    float* o1 = out + (fg + 64) * MPAD + pg * 8;
#pragma unroll
    for (int mp = 0; mp < 4; mp++) {
        float2 v = funpack(acc[mp][0]);
        *(ull*)(o0 + 2 * mp) = fpack(fmaxf(v.x, 0.f), fmaxf(v.y, 0.f));
        float2 u = funpack(acc[mp][1]);
        *(ull*)(o1 + 2 * mp) = fpack(fmaxf(u.x, 0.f), fmaxf(u.y, 0.f));
    }
}

// ---------------- Kernel 1: persistent pair-MLP ----------------
// Smem layout (floats):
//   W1s [64][128]  @ 0      (8192)
//   W2s [128][128] @ 8192   (16384)
//   W3s [128][128] @ 24576  (16384)
//   bufA [128][34] @ 40960  (4352)
//   bufB [128][34] @ 45312  (4352)
//   accs [4][128]  @ 49664  (512)
// total 50176 floats = 200704 bytes
#define SMEM_FLOATS 50176
#define SMEM_BYTES (SMEM_FLOATS * 4)

__global__ void __launch_bounds__(256, 1)
pair_mlp_kernel(const float* __restrict__ W1, const float* __restrict__ b1,
                const float* __restrict__ W2, const float* __restrict__ b2,
                const float* __restrict__ W3, const float* __restrict__ b3) {
    extern __shared__ float smem[];
    float* W1s  = smem;
    float* W2s  = smem + 8192;
    float* W3s  = smem + 24576;
    float* bufA = smem + 40960;
    float* bufB = smem + 45312;
    float* accs = smem + 49664;

    int tid = threadIdx.x;
    int fg = tid & 63;
    int pg = tid >> 6;

    // Cooperative weight load (once per persistent CTA)
    for (int i = tid; i < 2048; i += 256) ((float4*)W1s)[i] = ((const float4*)W1)[i];
    for (int i = tid; i < 4096; i += 256) ((float4*)W2s)[i] = ((const float4*)W2)[i];
    for (int i = tid; i < 4096; i += 256) ((float4*)W3s)[i] = ((const float4*)W3)[i];
    for (int i = tid; i < BB * HH; i += 256) accs[i] = 0.f;

    float b1_0 = b1[fg], b1_1 = b1[fg + 64];
    float b2_0 = b2[fg], b2_1 = b2[fg + 64];
    float b3_0 = b3[fg], b3_1 = b3[fg + 64];
    __syncthreads();

    for (int t = blockIdx.x; t < NTILES; t += gridDim.x) {
        int b = t / TILES_PER_B;
        int tt = t - b * TILES_PER_B;
        // Map triangular tile index -> (row i, j-chunk jt).
        // Rows [32g, 32g+32) all have c = 8-g chunks of 32 js starting at j=i.
        int g = 0, rem = tt;
        while (rem >= 32 * (8 - g)) { rem -= 32 * (8 - g); ++g; }
        int c = 8 - g;
        int i = 32 * g + rem / c;
        int jt = rem - (rem / c) * c;
        int j0 = i + 32 * jt;

        __syncthreads();  // prev tile done reading bufA

        // Build p tile: bufA[k][m] = x[b,i,k] * x[b,j0+m,k], K-major
        {
            int m = tid & 31;
            int k0 = (tid >> 5) * 8;
            int j = j0 + m; if (j > NN - 1) j = NN - 1;  // clamp; weight 0 later
            const float* xip = g_x + (b * NN + i) * DD + k0;
            const float* xjp = g_x + (b * NN + j) * DD + k0;
            float4 xi0 = *(const float4*)xip, xi1 = *(const float4*)(xip + 4);
            float4 xj0 = *(const float4*)xjp, xj1 = *(const float4*)(xjp + 4);
            float* pp = bufA + k0 * MPAD + m;
            pp[0 * MPAD] = xi0.x * xj0.x;
            pp[1 * MPAD] = xi0.y * xj0.y;
            pp[2 * MPAD] = xi0.z * xj0.z;
            pp[3 * MPAD] = xi0.w * xj0.w;
            pp[4 * MPAD] = xi1.x * xj1.x;
            pp[5 * MPAD] = xi1.y * xj1.y;
            pp[6 * MPAD] = xi1.z * xj1.z;
            pp[7 * MPAD] = xi1.w * xj1.w;
        }
        __syncthreads();

        ull acc[4][2];
        gemm_acc<DD>(bufA, W1s, pg, fg, b1_0, b1_1, acc);   // layer 1 (K=64)
        store_relu(bufB, pg, fg, acc);
        __syncthreads();
        gemm_acc<HH>(bufB, W2s, pg, fg, b2_0, b2_1, acc);   // layer 2
        store_relu(bufA, pg, fg, acc);
        __syncthreads();
        gemm_acc<HH>(bufA, W3s, pg, fg, b3_0, b3_1, acc);   // layer 3 -> regs

        // relu + symmetric weighting, reduce over this thread's 8 pairs
        float r0 = 0.f, r1 = 0.f;
#pragma unroll
        for (int mp = 0; mp < 4; mp++) {
            float2 v0 = funpack(acc[mp][0]);
            float2 v1 = funpack(acc[mp][1]);
            int m0 = pg * 8 + 2 * mp;
            int ja = j0 + m0, jb = j0 + m0 + 1;
            float wa = (ja > NN - 1) ? 0.f : ((ja == i) ? 1.f : 2.f);
            float wb = (jb > NN - 1) ? 0.f : ((jb == i) ? 1.f : 2.f);
            r0 += wa * fmaxf(v0.x, 0.f) + wb * fmaxf(v0.y, 0.f);
            r1 += wa * fmaxf(v1.x, 0.f) + wb * fmaxf(v1.y, 0.f);
        }
        // Deterministic smem accumulation: serialize the 4 pair-groups
#pragma unroll
        for (int turn = 0; turn < 4; turn++) {
            if (pg == turn) {
                accs[b * HH + fg]      += r0;
                accs[b * HH + fg + 64] += r1;
            }
            __syncthreads();
        }
    }

    // Flush partials (deterministic per-CTA slot, no atomics)
    for (int idx = tid; idx < BB * HH; idx += 256)
        g_partial[blockIdx.x * (BB * HH) + idx] = accs[idx];
}

// ---------------- Kernel 2: reduce + mean + relu + decoder MLP ----------------
__global__ void finalize_kernel(const float* __restrict__ D1, const float* __restrict__ c1,
                                const float* __restrict__ D2, const float* __restrict__ c2,
                                const float* __restrict__ D3, const float* __restrict__ c3,
                                float* __restrict__ out) {
    __shared__ float ha[BB * HH];
    __shared__ float hb[BB * HH];
    int tid = threadIdx.x;          // 0..511
    float s = 0.f;
    for (int cta = 0; cta < GRID1; cta++)      // fixed order -> deterministic
        s += g_partial[cta * (BB * HH) + tid];
    s *= (1.0f / (float)(NN * NN));            // mean over (i,j)
    ha[tid] = fmaxf(s, 0.f);                   // relu
    __syncthreads();

    int b = tid >> 7, f = tid & 127;
    float v = c1[f];
    for (int k = 0; k < HH; k++) v += ha[b * HH + k] * D1[k * HH + f];
    hb[tid] = fmaxf(v, 0.f);
    __syncthreads();

    v = c2[f];
    for (int k = 0; k < HH; k++) v += hb[b * HH + k] * D2[k * HH + f];
    ha[tid] = fmaxf(v, 0.f);
    __syncthreads();

    if (tid < BB) {
        float o = c3[0];
        for (int k = 0; k < HH; k++) o += ha[tid * HH + k] * D3[k];
        out[tid] = o;
    }
}

// ---------------- Launch ----------------
extern "C" void kernel_launch(void* const* d_in, const int* in_sizes, int n_in,
                              void* d_out, int out_size) {
    const int*   xcat  = (const int*)d_in[0];
    const float* xfeat = (const float*)d_in[1];
    const float* emb   = (const float*)d_in[2];
    const float* W1 = (const float*)d_in[3];
    const float* b1 = (const float*)d_in[4];
    const float* W2 = (const float*)d_in[5];
    const float* b2 = (const float*)d_in[6];
    const float* W3 = (const float*)d_in[7];
    const float* b3 = (const float*)d_in[8];
    const float* D1 = (const float*)d_in[9];
    const float* c1 = (const float*)d_in[10];
    const float* D2 = (const float*)d_in[11];
    const float* c2 = (const float*)d_in[12];
    const float* D3 = (const float*)d_in[13];
    const float* c3 = (const float*)d_in[14];
    float* out = (float*)d_out;

    cudaFuncSetAttribute(pair_mlp_kernel,
                         cudaFuncAttributeMaxDynamicSharedMemorySize, SMEM_BYTES);

    build_x_kernel<<<BB * NN, DD>>>(xcat, xfeat, emb);
    pair_mlp_kernel<<<GRID1, 256, SMEM_BYTES>>>(W1, b1, W2, b2, W3, b3);
    finalize_kernel<<<1, 512>>>(D1, c1, D2, c2, D3, c3, out);
}

// round 3
// speedup vs baseline: 2.3509x; 2.3509x over previous
#include <cuda_runtime.h>
#include <cuda_bf16.h>
#include <cstdint>

// Problem constants
#define BB 4
#define NN 256
#define EE 63
#define DD 64
#define HH 128

// Tiles: (b, i, jc). i<128: jc in {0,1}; i>=128: jc=1.  384 per b.
#define TILES_PER_B 384
#define NTILES (BB * TILES_PER_B)
#define GRID1 152

#define APITCH 136      // bf16 elements per row (68 words: pitch%32words==4 -> conflict-free)
#define W1PITCH 72      // bf16 elements per row for W1 (36 words)

// SMEM layout (bytes)
#define OFF_W1H 0
#define OFF_W1L 18432
#define OFF_W2H 36864
#define OFF_W2L 71680
#define OFF_W3H 106496
#define OFF_W3L 141312
#define OFF_ACT 176128
#define OFF_B1  210944
#define OFF_B2  211456
#define OFF_B3  211968
#define OFF_ACCS 212480          // float accs[4 strips][BB][HH] = 8192 B
#define SMEM_BYTES 220672

// Scratch (no allocations allowed)
__device__ float g_x[BB * NN * DD];
__device__ float g_partial[GRID1 * BB * HH];

// ---------------- Kernel 0: build x = concat(emb[xcat], xfeat) ----------------
__global__ void build_x_kernel(const int* __restrict__ xcat32,
                               const float* __restrict__ xfeat,
                               const float* __restrict__ emb) {
    int row = blockIdx.x;
    int d = threadIdx.x;
    // int64-vs-int32 detection (odd words all zero => int64 source)
    bool is64 = (xcat32[1] == 0) && (xcat32[3] == 0) && (xcat32[5] == 0) &&
                (xcat32[7] == 0) && (xcat32[9] == 0) && (xcat32[11] == 0);
    int idx = is64 ? xcat32[row * 2] : xcat32[row];
    float v = (d < EE) ? emb[idx * EE + d] : xfeat[row];
    g_x[row * DD + d] = v;
}

// ---------------- HMMA m16n8k16 bf16 (plain PTX, compute_80+) ----------------
__device__ __forceinline__ void mma16816(float& c0, float& c1, float& c2, float& c3,
                                         uint32_t a0, uint32_t a1, uint32_t a2, uint32_t a3,
                                         uint32_t b0, uint32_t b1) {
    asm volatile("mma.sync.aligned.m16n8k16.row.col.f32.bf16.bf16.f32 "
                 "{%0,%1,%2,%3}, {%4,%5,%6,%7}, {%8,%9}, {%0,%1,%2,%3};"
                 : "+f"(c0), "+f"(c1), "+f"(c2), "+f"(c3)
                 : "r"(a0), "r"(a1), "r"(a2), "r"(a3), "r"(b0), "r"(b1));
}

__device__ __forceinline__ uint32_t lds32(const __nv_bfloat16* p) {
    return *(const uint32_t*)p;      // 4B-aligned: element index always even
}

// One GEMM layer: c[m][f] = bias[f] + sum_k act[m][k] * (Wh+Wl)[f][k]
// Warp tile: 32 m-rows (m0..m0+31) x 64 f-cols (f0..f0+63).
template <int KSTEPS>
__device__ __forceinline__ void run_layer(const __nv_bfloat16* __restrict__ act,
                                          const __nv_bfloat16* __restrict__ Wh,
                                          const __nv_bfloat16* __restrict__ Wl,
                                          int wpitch, const float* __restrict__ bias,
                                          int m0, int f0, int g, int tig,
                                          float c[2][8][4]) {
#pragma unroll
    for (int nt = 0; nt < 8; nt++) {
        float2 bv = *(const float2*)(bias + f0 + nt * 8 + 2 * tig);
#pragma unroll
        for (int mt = 0; mt < 2; mt++) {
            c[mt][nt][0] = bv.x; c[mt][nt][1] = bv.y;
            c[mt][nt][2] = bv.x; c[mt][nt][3] = bv.y;
        }
    }
#pragma unroll 2
    for (int ks = 0; ks < KSTEPS; ks++) {
        int k = ks * 16 + 2 * tig;
        uint32_t a[2][4];
#pragma unroll
        for (int mt = 0; mt < 2; mt++) {
            const __nv_bfloat16* ar = act + (m0 + mt * 16 + g) * APITCH + k;
            a[mt][0] = lds32(ar);                 // (row g,   k0)
            a[mt][1] = lds32(ar + 8 * APITCH);    // (row g+8, k0)
            a[mt][2] = lds32(ar + 8);             // (row g,   k0+8)
            a[mt][3] = lds32(ar + 8 * APITCH + 8);
        }
#pragma unroll
        for (int nt = 0; nt < 8; nt++) {
            const __nv_bfloat16* wh = Wh + (f0 + nt * 8 + g) * wpitch + k;
            const __nv_bfloat16* wl = Wl + (f0 + nt * 8 + g) * wpitch + k;
            uint32_t bh0 = lds32(wh), bh1 = lds32(wh + 8);
            uint32_t bl0 = lds32(wl), bl1 = lds32(wl + 8);
#pragma unroll
            for (int mt = 0; mt < 2; mt++) {
                mma16816(c[mt][nt][0], c[mt][nt][1], c[mt][nt][2], c[mt][nt][3],
                         a[mt][0], a[mt][1], a[mt][2], a[mt][3], bh0, bh1);
                mma16816(c[mt][nt][0], c[mt][nt][1], c[mt][nt][2], c[mt][nt][3],
                         a[mt][0], a[mt][1], a[mt][2], a[mt][3], bl0, bl1);
            }
        }
    }
}

// relu + store as next activation (bf16 hi only), conflict-free STS.32
__device__ __forceinline__ void store_act(__nv_bfloat16* __restrict__ act,
                                          int m0, int f0, int g, int tig,
                                          float c[2][8][4]) {
#pragma unroll
    for (int mt = 0; mt < 2; mt++) {
        int m = m0 + mt * 16 + g;
#pragma unroll
        for (int nt = 0; nt < 8; nt++) {
            int f = f0 + nt * 8 + 2 * tig;
            __nv_bfloat162 v;
            v.x = __float2bfloat16(fmaxf(c[mt][nt][0], 0.f));
            v.y = __float2bfloat16(fmaxf(c[mt][nt][1], 0.f));
            *(__nv_bfloat162*)(act + m * APITCH + f) = v;
            __nv_bfloat162 w;
            w.x = __float2bfloat16(fmaxf(c[mt][nt][2], 0.f));
            w.y = __float2bfloat16(fmaxf(c[mt][nt][3], 0.f));
            *(__nv_bfloat162*)(act + (m + 8) * APITCH + f) = w;
        }
    }
}

// Transpose + 2-way bf16 split of a weight matrix into SMEM: Wt[f][k]
__device__ void load_wt(const float* __restrict__ W, int K,
                        __nv_bfloat16* hi, __nv_bfloat16* lo, int pitch, int tid) {
    for (int idx = tid; idx < K * HH; idx += 256) {
        int f = idx & 127, k = idx >> 7;
        float w = W[k * HH + f];
        __nv_bfloat16 h = __float2bfloat16(w);
        float r = w - __bfloat162float(h);
        hi[f * pitch + k] = h;
        lo[f * pitch + k] = __float2bfloat16(r);
    }
}

// ---------------- Kernel 1: persistent HMMA pair-MLP ----------------
__global__ void __launch_bounds__(256, 1)
pair_mlp_kernel(const float* __restrict__ W1, const float* __restrict__ b1,
                const float* __restrict__ W2, const float* __restrict__ b2,
                const float* __restrict__ W3, const float* __restrict__ b3) {
    extern __shared__ char sm[];
    __nv_bfloat16* W1h = (__nv_bfloat16*)(sm + OFF_W1H);
    __nv_bfloat16* W1l = (__nv_bfloat16*)(sm + OFF_W1L);
    __nv_bfloat16* W2h = (__nv_bfloat16*)(sm + OFF_W2H);
    __nv_bfloat16* W2l = (__nv_bfloat16*)(sm + OFF_W2L);
    __nv_bfloat16* W3h = (__nv_bfloat16*)(sm + OFF_W3H);
    __nv_bfloat16* W3l = (__nv_bfloat16*)(sm + OFF_W3L);
    __nv_bfloat16* act = (__nv_bfloat16*)(sm + OFF_ACT);
    float* b1s = (float*)(sm + OFF_B1);
    float* b2s = (float*)(sm + OFF_B2);
    float* b3s = (float*)(sm + OFF_B3);
    float* accs = (float*)(sm + OFF_ACCS);   // [4 strips][BB][HH]

    const int tid = threadIdx.x;
    const int warp = tid >> 5, lane = tid & 31;
    const int g = lane >> 2, tig = lane & 3;
    const int m0 = (warp >> 1) * 32;         // pair strip
    const int f0 = (warp & 1) * 64;          // feature half
    const int strip = warp >> 1;

    load_wt(W1, DD, W1h, W1l, W1PITCH, tid);
    load_wt(W2, HH, W2h, W2l, APITCH, tid);
    load_wt(W3, HH, W3h, W3l, APITCH, tid);
    if (tid < 128) { b1s[tid] = b1[tid]; b2s[tid] = b2[tid]; b3s[tid] = b3[tid]; }
    for (int idx = tid; idx < 4 * BB * HH; idx += 256) accs[idx] = 0.f;
    __syncthreads();

    float c[2][8][4];

    for (int t = blockIdx.x; t < NTILES; t += GRID1) {
        int b = t / TILES_PER_B;
        int r = t - b * TILES_PER_B;
        int i, jc;
        if (r < 256) { i = r >> 1; jc = r & 1; }
        else         { i = r - 128; jc = 1; }
        int j0 = jc << 7;

        // ---- build p tile: act[m][k] = bf16(x[b,i,k] * x[b,j0+m,k]) ----
        {
            int m = tid >> 1;
            int kh = (tid & 1) * 32;
            const float4* xi = (const float4*)(g_x + (b * NN + i) * DD + kh);
            const float4* xj = (const float4*)(g_x + (b * NN + j0 + m) * DD + kh);
            __nv_bfloat16* row = act + m * APITCH + kh;
#pragma unroll
            for (int q = 0; q < 8; q++) {
                float4 a4 = xi[q], c4 = xj[q];
                __nv_bfloat162 v, w;
                v.x = __float2bfloat16(a4.x * c4.x);
                v.y = __float2bfloat16(a4.y * c4.y);
                w.x = __float2bfloat16(a4.z * c4.z);
                w.y = __float2bfloat16(a4.w * c4.w);
                *(__nv_bfloat162*)(row + q * 4)     = v;
                *(__nv_bfloat162*)(row + q * 4 + 2) = w;
            }
        }
        __syncthreads();

        // Layer 1 (K=64)
        run_layer<4>(act, W1h, W1l, W1PITCH, b1s, m0, f0, g, tig, c);
        __syncthreads();
        store_act(act, m0, f0, g, tig, c);
        __syncthreads();

        // Layer 2 (K=128)
        run_layer<8>(act, W2h, W2l, APITCH, b2s, m0, f0, g, tig, c);
        __syncthreads();
        store_act(act, m0, f0, g, tig, c);
        __syncthreads();

        // Layer 3 (K=128) -> relu + symmetric weight + pooled reduce
        run_layer<8>(act, W3h, W3l, APITCH, b3s, m0, f0, g, tig, c);
#pragma unroll
        for (int nt = 0; nt < 8; nt++) {
            float s0 = 0.f, s1 = 0.f;
#pragma unroll
            for (int mt = 0; mt < 2; mt++) {
                int m = m0 + mt * 16 + g;
                int ja = j0 + m, jb = j0 + m + 8;
                float wa = (ja < i) ? 0.f : ((ja == i) ? 1.f : 2.f);
                float wb = (jb < i) ? 0.f : ((jb == i) ? 1.f : 2.f);
                s0 += wa * fmaxf(c[mt][nt][0], 0.f) + wb * fmaxf(c[mt][nt][2], 0.f);
                s1 += wa * fmaxf(c[mt][nt][1], 0.f) + wb * fmaxf(c[mt][nt][3], 0.f);
            }
            s0 += __shfl_xor_sync(0xffffffffu, s0, 4);
            s0 += __shfl_xor_sync(0xffffffffu, s0, 8);
            s0 += __shfl_xor_sync(0xffffffffu, s0, 16);
            s1 += __shfl_xor_sync(0xffffffffu, s1, 4);
            s1 += __shfl_xor_sync(0xffffffffu, s1, 8);
            s1 += __shfl_xor_sync(0xffffffffu, s1, 16);
            if (lane < 4) {   // lane==tig, g==0
                float* ap = accs + (strip * BB + b) * HH + f0 + nt * 8 + 2 * tig;
                ap[0] += s0;
                ap[1] += s1;
            }
        }
        __syncthreads();   // layer-3 reads done before next p-build overwrites act
    }

    // flush: sum the 4 strips, one slot per CTA (deterministic)
    for (int idx = tid; idx < BB * HH; idx += 256) {
        float s = accs[idx] + accs[BB * HH + idx] +
                  accs[2 * BB * HH + idx] + accs[3 * BB * HH + idx];
        g_partial[blockIdx.x * (BB * HH) + idx] = s;
    }
}

// ---------------- Kernel 2: reduce + mean + relu + decoder MLP ----------------
__global__ void finalize_kernel(const float* __restrict__ D1, const float* __restrict__ c1,
                                const float* __restrict__ D2, const float* __restrict__ c2,
                                const float* __restrict__ D3, const float* __restrict__ c3,
                                float* __restrict__ out) {
    __shared__ float ha[BB * HH];
    __shared__ float hb[BB * HH];
    int tid = threadIdx.x;          // 0..511
    float s = 0.f;
    for (int cta = 0; cta < GRID1; cta++)
        s += g_partial[cta * (BB * HH) + tid];
    s *= (1.0f / (float)(NN * NN));
    ha[tid] = fmaxf(s, 0.f);
    __syncthreads();

    int b = tid >> 7, f = tid & 127;
    float v = c1[f];
    for (int k = 0; k < HH; k++) v += ha[b * HH + k] * D1[k * HH + f];
    hb[tid] = fmaxf(v, 0.f);
    __syncthreads();

    v = c2[f];
    for (int k = 0; k < HH; k++) v += hb[b * HH + k] * D2[k * HH + f];
    ha[tid] = fmaxf(v, 0.f);
    __syncthreads();

    if (tid < BB) {
        float o = c3[0];
        for (int k = 0; k < HH; k++) o += ha[tid * HH + k] * D3[k];
        out[tid] = o;
    }
}

// ---------------- Launch ----------------
extern "C" void kernel_launch(void* const* d_in, const int* in_sizes, int n_in,
                              void* d_out, int out_size) {
    const int*   xcat  = (const int*)d_in[0];
    const float* xfeat = (const float*)d_in[1];
    const float* emb   = (const float*)d_in[2];
    const float* W1 = (const float*)d_in[3];
    const float* b1 = (const float*)d_in[4];
    const float* W2 = (const float*)d_in[5];
    const float* b2 = (const float*)d_in[6];
    const float* W3 = (const float*)d_in[7];
    const float* b3 = (const float*)d_in[8];
    const float* D1 = (const float*)d_in[9];
    const float* c1 = (const float*)d_in[10];
    const float* D2 = (const float*)d_in[11];
    const float* c2 = (const float*)d_in[12];
    const float* D3 = (const float*)d_in[13];
    const float* c3 = (const float*)d_in[14];
    float* out = (float*)d_out;

    cudaFuncSetAttribute(pair_mlp_kernel,
                         cudaFuncAttributeMaxDynamicSharedMemorySize, SMEM_BYTES);

    build_x_kernel<<<BB * NN, DD>>>(xcat, xfeat, emb);
    pair_mlp_kernel<<<GRID1, 256, SMEM_BYTES>>>(W1, b1, W2, b2, W3, b3);
    finalize_kernel<<<1, 512>>>(D1, c1, D2, c2, D3, c3, out);
}

// round 4
// speedup vs baseline: 3.1315x; 1.3320x over previous
#include <cuda_runtime.h>
#include <cuda_bf16.h>
#include <cstdint>

// Problem constants
#define BB 4
#define NN 256
#define EE 63
#define DD 64
#define HH 128

// Exact triangular packing: per b, 256*257/2 = 32896 pairs = 257 tiles of 128.
#define TILES_PER_B 257
#define NTILES (BB * TILES_PER_B)
#define GRID1 152

#define APITCH 136      // bf16 elements per row (68 words: conflict-free)
#define W1PITCH 72

// SMEM layout (bytes)
#define OFF_W1H 0
#define OFF_W1L 18432
#define OFF_W2H 36864
#define OFF_W2L 71680
#define OFF_W3H 106496
#define OFF_W3L 141312
#define OFF_ACT 176128
#define OFF_B1  210944
#define OFF_B2  211456
#define OFF_B3  211968
#define OFF_ACCS 212480          // float accs[4 strips][BB][HH] = 8192 B
#define SMEM_BYTES 220672

// Scratch
__device__ float g_x[BB * NN * DD];
__device__ float g_partial[GRID1 * BB * HH];

// flat triangular index p in [0, 32896) -> (i, j), j >= i
__device__ __forceinline__ int2 pair_from_flat(int p) {
    int i = (int)(256.5f - sqrtf(65792.25f - 2.0f * (float)p));
    // integer fixup for float rounding at boundaries
    while (i * 256 - (i * (i - 1)) / 2 > p) --i;
    while ((i + 1) * 256 - ((i + 1) * i) / 2 <= p) ++i;
    int j = i + (p - (i * 256 - (i * (i - 1)) / 2));
    return make_int2(i, j);
}

// ---------------- Kernel 0: build x = concat(emb[xcat], xfeat) ----------------
__global__ void build_x_kernel(const int* __restrict__ xcat32,
                               const float* __restrict__ xfeat,
                               const float* __restrict__ emb) {
    int row = blockIdx.x;
    int d = threadIdx.x;
    bool is64 = (xcat32[1] == 0) && (xcat32[3] == 0) && (xcat32[5] == 0) &&
                (xcat32[7] == 0) && (xcat32[9] == 0) && (xcat32[11] == 0);
    int idx = is64 ? xcat32[row * 2] : xcat32[row];
    float v = (d < EE) ? emb[idx * EE + d] : xfeat[row];
    g_x[row * DD + d] = v;
}

// ---------------- HMMA m16n8k16 bf16 ----------------
__device__ __forceinline__ void mma16816(float& c0, float& c1, float& c2, float& c3,
                                         uint32_t a0, uint32_t a1, uint32_t a2, uint32_t a3,
                                         uint32_t b0, uint32_t b1) {
    asm volatile("mma.sync.aligned.m16n8k16.row.col.f32.bf16.bf16.f32 "
                 "{%0,%1,%2,%3}, {%4,%5,%6,%7}, {%8,%9}, {%0,%1,%2,%3};"
                 : "+f"(c0), "+f"(c1), "+f"(c2), "+f"(c3)
                 : "r"(a0), "r"(a1), "r"(a2), "r"(a3), "r"(b0), "r"(b1));
}

__device__ __forceinline__ uint32_t lds32(const __nv_bfloat16* p) {
    return *(const uint32_t*)p;
}

template <int KSTEPS>
__device__ __forceinline__ void run_layer(const __nv_bfloat16* __restrict__ act,
                                          const __nv_bfloat16* __restrict__ Wh,
                                          const __nv_bfloat16* __restrict__ Wl,
                                          int wpitch, const float* __restrict__ bias,
                                          int m0, int f0, int g, int tig,
                                          float c[2][8][4]) {
#pragma unroll
    for (int nt = 0; nt < 8; nt++) {
        float2 bv = *(const float2*)(bias + f0 + nt * 8 + 2 * tig);
#pragma unroll
        for (int mt = 0; mt < 2; mt++) {
            c[mt][nt][0] = bv.x; c[mt][nt][1] = bv.y;
            c[mt][nt][2] = bv.x; c[mt][nt][3] = bv.y;
        }
    }
#pragma unroll 2
    for (int ks = 0; ks < KSTEPS; ks++) {
        int k = ks * 16 + 2 * tig;
        uint32_t a[2][4];
#pragma unroll
        for (int mt = 0; mt < 2; mt++) {
            const __nv_bfloat16* ar = act + (m0 + mt * 16 + g) * APITCH + k;
            a[mt][0] = lds32(ar);
            a[mt][1] = lds32(ar + 8 * APITCH);
            a[mt][2] = lds32(ar + 8);
            a[mt][3] = lds32(ar + 8 * APITCH + 8);
        }
#pragma unroll
        for (int nt = 0; nt < 8; nt++) {
            const __nv_bfloat16* wh = Wh + (f0 + nt * 8 + g) * wpitch + k;
            const __nv_bfloat16* wl = Wl + (f0 + nt * 8 + g) * wpitch + k;
            uint32_t bh0 = lds32(wh), bh1 = lds32(wh + 8);
            uint32_t bl0 = lds32(wl), bl1 = lds32(wl + 8);
#pragma unroll
            for (int mt = 0; mt < 2; mt++) {
                mma16816(c[mt][nt][0], c[mt][nt][1], c[mt][nt][2], c[mt][nt][3],
                         a[mt][0], a[mt][1], a[mt][2], a[mt][3], bh0, bh1);
                mma16816(c[mt][nt][0], c[mt][nt][1], c[mt][nt][2], c[mt][nt][3],
                         a[mt][0], a[mt][1], a[mt][2], a[mt][3], bl0, bl1);
            }
        }
    }
}

__device__ __forceinline__ void store_act(__nv_bfloat16* __restrict__ act,
                                          int m0, int f0, int g, int tig,
                                          float c[2][8][4]) {
#pragma unroll
    for (int mt = 0; mt < 2; mt++) {
        int m = m0 + mt * 16 + g;
#pragma unroll
        for (int nt = 0; nt < 8; nt++) {
            int f = f0 + nt * 8 + 2 * tig;
            __nv_bfloat162 v;
            v.x = __float2bfloat16(fmaxf(c[mt][nt][0], 0.f));
            v.y = __float2bfloat16(fmaxf(c[mt][nt][1], 0.f));
            *(__nv_bfloat162*)(act + m * APITCH + f) = v;
            __nv_bfloat162 w;
            w.x = __float2bfloat16(fmaxf(c[mt][nt][2], 0.f));
            w.y = __float2bfloat16(fmaxf(c[mt][nt][3], 0.f));
            *(__nv_bfloat162*)(act + (m + 8) * APITCH + f) = w;
        }
    }
}

__device__ void load_wt(const float* __restrict__ W, int K,
                        __nv_bfloat16* hi, __nv_bfloat16* lo, int pitch, int tid) {
    for (int idx = tid; idx < K * HH; idx += 256) {
        int f = idx & 127, k = idx >> 7;
        float w = W[k * HH + f];
        __nv_bfloat16 h = __float2bfloat16(w);
        float r = w - __bfloat162float(h);
        hi[f * pitch + k] = h;
        lo[f * pitch + k] = __float2bfloat16(r);
    }
}

// ---------------- Kernel 1: persistent HMMA pair-MLP (packed pairs) ----------------
__global__ void __launch_bounds__(256, 1)
pair_mlp_kernel(const float* __restrict__ W1, const float* __restrict__ b1,
                const float* __restrict__ W2, const float* __restrict__ b2,
                const float* __restrict__ W3, const float* __restrict__ b3) {
    extern __shared__ char sm[];
    __nv_bfloat16* W1h = (__nv_bfloat16*)(sm + OFF_W1H);
    __nv_bfloat16* W1l = (__nv_bfloat16*)(sm + OFF_W1L);
    __nv_bfloat16* W2h = (__nv_bfloat16*)(sm + OFF_W2H);
    __nv_bfloat16* W2l = (__nv_bfloat16*)(sm + OFF_W2L);
    __nv_bfloat16* W3h = (__nv_bfloat16*)(sm + OFF_W3H);
    __nv_bfloat16* W3l = (__nv_bfloat16*)(sm + OFF_W3L);
    __nv_bfloat16* act = (__nv_bfloat16*)(sm + OFF_ACT);
    float* b1s = (float*)(sm + OFF_B1);
    float* b2s = (float*)(sm + OFF_B2);
    float* b3s = (float*)(sm + OFF_B3);
    float* accs = (float*)(sm + OFF_ACCS);

    const int tid = threadIdx.x;
    const int warp = tid >> 5, lane = tid & 31;
    const int g = lane >> 2, tig = lane & 3;
    const int m0 = (warp >> 1) * 32;
    const int f0 = (warp & 1) * 64;
    const int strip = warp >> 1;

    load_wt(W1, DD, W1h, W1l, W1PITCH, tid);
    load_wt(W2, HH, W2h, W2l, APITCH, tid);
    load_wt(W3, HH, W3h, W3l, APITCH, tid);
    if (tid < 128) { b1s[tid] = b1[tid]; b2s[tid] = b2[tid]; b3s[tid] = b3[tid]; }
    for (int idx = tid; idx < 4 * BB * HH; idx += 256) accs[idx] = 0.f;
    __syncthreads();

    float c[2][8][4];

    for (int t = blockIdx.x; t < NTILES; t += GRID1) {
        int b = t / TILES_PER_B;
        int r = t - b * TILES_PER_B;
        int P0 = r * 128;                 // flat pair base for this tile

        // ---- build p tile: act[m][k] = bf16(x[b,im,k] * x[b,jm,k]) ----
        {
            int m = tid >> 1;
            int kh = (tid & 1) * 32;
            int2 ij = pair_from_flat(P0 + m);
            const float4* xi = (const float4*)(g_x + (b * NN + ij.x) * DD + kh);
            const float4* xj = (const float4*)(g_x + (b * NN + ij.y) * DD + kh);
            __nv_bfloat16* row = act + m * APITCH + kh;
#pragma unroll
            for (int q = 0; q < 8; q++) {
                float4 a4 = xi[q], c4 = xj[q];
                __nv_bfloat162 v, w;
                v.x = __float2bfloat16(a4.x * c4.x);
                v.y = __float2bfloat16(a4.y * c4.y);
                w.x = __float2bfloat16(a4.z * c4.z);
                w.y = __float2bfloat16(a4.w * c4.w);
                *(__nv_bfloat162*)(row + q * 4)     = v;
                *(__nv_bfloat162*)(row + q * 4 + 2) = w;
            }
        }
        __syncthreads();

        run_layer<4>(act, W1h, W1l, W1PITCH, b1s, m0, f0, g, tig, c);
        __syncthreads();
        store_act(act, m0, f0, g, tig, c);
        __syncthreads();

        run_layer<8>(act, W2h, W2l, APITCH, b2s, m0, f0, g, tig, c);
        __syncthreads();
        store_act(act, m0, f0, g, tig, c);
        __syncthreads();

        run_layer<8>(act, W3h, W3l, APITCH, b3s, m0, f0, g, tig, c);

        // symmetric multiplicity: 1 on diagonal (i==j), 2 off-diagonal
        float wm[2][2];
#pragma unroll
        for (int mt = 0; mt < 2; mt++) {
#pragma unroll
            for (int h = 0; h < 2; h++) {
                int2 ij = pair_from_flat(P0 + m0 + mt * 16 + g + h * 8);
                wm[mt][h] = (ij.x == ij.y) ? 1.f : 2.f;
            }
        }
#pragma unroll
        for (int nt = 0; nt < 8; nt++) {
            float s0 = 0.f, s1 = 0.f;
#pragma unroll
            for (int mt = 0; mt < 2; mt++) {
                s0 += wm[mt][0] * fmaxf(c[mt][nt][0], 0.f) + wm[mt][1] * fmaxf(c[mt][nt][2], 0.f);
                s1 += wm[mt][0] * fmaxf(c[mt][nt][1], 0.f) + wm[mt][1] * fmaxf(c[mt][nt][3], 0.f);
            }
            s0 += __shfl_xor_sync(0xffffffffu, s0, 4);
            s0 += __shfl_xor_sync(0xffffffffu, s0, 8);
            s0 += __shfl_xor_sync(0xffffffffu, s0, 16);
            s1 += __shfl_xor_sync(0xffffffffu, s1, 4);
            s1 += __shfl_xor_sync(0xffffffffu, s1, 8);
            s1 += __shfl_xor_sync(0xffffffffu, s1, 16);
            if (lane < 4) {
                float* ap = accs + (strip * BB + b) * HH + f0 + nt * 8 + 2 * tig;
                ap[0] += s0;
                ap[1] += s1;
            }
        }
        __syncthreads();
    }

    for (int idx = tid; idx < BB * HH; idx += 256) {
        float s = accs[idx] + accs[BB * HH + idx] +
                  accs[2 * BB * HH + idx] + accs[3 * BB * HH + idx];
        g_partial[blockIdx.x * (BB * HH) + idx] = s;
    }
}

// ---------------- Kernel 2: reduce + mean + relu + decoder MLP ----------------
__global__ void finalize_kernel(const float* __restrict__ D1, const float* __restrict__ c1,
                                const float* __restrict__ D2, const float* __restrict__ c2,
                                const float* __restrict__ D3, const float* __restrict__ c3,
                                float* __restrict__ out) {
    __shared__ float ha[BB * HH];
    __shared__ float hb[BB * HH];
    int tid = threadIdx.x;
    float s = 0.f;
    for (int cta = 0; cta < GRID1; cta++)
        s += g_partial[cta * (BB * HH) + tid];
    s *= (1.0f / (float)(NN * NN));
    ha[tid] = fmaxf(s, 0.f);
    __syncthreads();

    int b = tid >> 7, f = tid & 127;
    float v = c1[f];
    for (int k = 0; k < HH; k++) v += ha[b * HH + k] * D1[k * HH + f];
    hb[tid] = fmaxf(v, 0.f);
    __syncthreads();

    v = c2[f];
    for (int k = 0; k < HH; k++) v += hb[b * HH + k] * D2[k * HH + f];
    ha[tid] = fmaxf(v, 0.f);
    __syncthreads();

    if (tid < BB) {
        float o = c3[0];
        for (int k = 0; k < HH; k++) o += ha[tid * HH + k] * D3[k];
        out[tid] = o;
    }
}

// ---------------- Launch ----------------
extern "C" void kernel_launch(void* const* d_in, const int* in_sizes, int n_in,
                              void* d_out, int out_size) {
    const int*   xcat  = (const int*)d_in[0];
    const float* xfeat = (const float*)d_in[1];
    const float* emb   = (const float*)d_in[2];
    const float* W1 = (const float*)d_in[3];
    const float* b1 = (const float*)d_in[4];
    const float* W2 = (const float*)d_in[5];
    const float* b2 = (const float*)d_in[6];
    const float* W3 = (const float*)d_in[7];
    const float* b3 = (const float*)d_in[8];
    const float* D1 = (const float*)d_in[9];
    const float* c1 = (const float*)d_in[10];
    const float* D2 = (const float*)d_in[11];
    const float* c2 = (const float*)d_in[12];
    const float* D3 = (const float*)d_in[13];
    const float* c3 = (const float*)d_in[14];
    float* out = (float*)d_out;

    cudaFuncSetAttribute(pair_mlp_kernel,
                         cudaFuncAttributeMaxDynamicSharedMemorySize, SMEM_BYTES);

    build_x_kernel<<<BB * NN, DD>>>(xcat, xfeat, emb);
    pair_mlp_kernel<<<GRID1, 256, SMEM_BYTES>>>(W1, b1, W2, b2, W3, b3);
    finalize_kernel<<<1, 512>>>(D1, c1, D2, c2, D3, c3, out);
}